// round 1
// baseline (speedup 1.0000x reference)
#include <cuda_runtime.h>
#include <math.h>

#define Bv 2
#define Cv 256
#define Hv 96
#define Wv 192
#define Gv 4
#define Kv 9
#define GC (Cv / Gv)      // 64 channels per group
#define HW (Hv * Wv)      // 18432

// NHWC scratch (allocation-free: __device__ globals). ~37.7MB each.
__device__ float g_right_nhwc[(size_t)Bv * Hv * Wv * Cv];
__device__ float g_left_nhwc[(size_t)Bv * Hv * Wv * Cv];

// ---------------------------------------------------------------------------
// NCHW -> NHWC transpose. Per (b,h) slice: transpose [C, W] (row stride HW)
// into [W, C]. W=192 and C=256 are multiples of 32 -> no bounds checks.
// grid: (W/32, C/32, B*H), block: (32, 8)
// ---------------------------------------------------------------------------
__global__ void nchw_to_nhwc_kernel(const float* __restrict__ in, float* __restrict__ out) {
    __shared__ float tile[32][33];
    int bh = blockIdx.z;
    int b = bh / Hv;
    int h = bh % Hv;
    const float* src = in + (size_t)b * Cv * HW + (size_t)h * Wv;
    int w0 = blockIdx.x * 32;
    int c0 = blockIdx.y * 32;
    int tx = threadIdx.x, ty = threadIdx.y;
#pragma unroll
    for (int i = 0; i < 32; i += 8) {
        tile[ty + i][tx] = src[(size_t)(c0 + ty + i) * HW + (w0 + tx)];
    }
    __syncthreads();
    float* dst = out + (size_t)bh * Wv * Cv;
#pragma unroll
    for (int i = 0; i < 32; i += 8) {
        dst[(size_t)(w0 + ty + i) * Cv + (c0 + tx)] = tile[tx][ty + i];
    }
}

// ---------------------------------------------------------------------------
// Correlation kernel. One 64-thread block per (b, h, w).
// Thread t handles channels [4t, 4t+4) as float4. k-loop fully unrolled.
// Group g = t/16 (16 threads x 4 ch = 64 ch); shfl reduction over 16 lanes.
// ---------------------------------------------------------------------------
__global__ __launch_bounds__(64) void corr_kernel(
    const float* __restrict__ flow,
    const float* __restrict__ extra,
    float* __restrict__ out)
{
    const int w = blockIdx.x;
    const int h = blockIdx.y;
    const int b = blockIdx.z;
    const int t = threadIdx.x;          // 0..63
    const int lane = t & 31;

    const int pix = h * Wv + w;

    const float4* leftp =
        (const float4*)(g_left_nhwc + ((size_t)(b * Hv + h) * Wv + w) * Cv);
    const float4 L = leftp[t];

    const float fx = flow[(size_t)(b * 2 + 0) * HW + pix];
    const float fy = flow[(size_t)(b * 2 + 1) * HW + pix];
    const float bx = (float)w + fx;
    const float by = (float)h + fy;

    const float* rbase = g_right_nhwc + (size_t)b * Hv * Wv * Cv;

#pragma unroll
    for (int k = 0; k < Kv; k++) {
        const float ex = extra[((size_t)(b * Kv + k) * 2 + 0) * HW + pix];
        const float ey = extra[((size_t)(b * Kv + k) * 2 + 1) * HW + pix];
        const float x = bx + (float)(k - 4) + ex;
        const float y = by + ey;

        const float x0f = floorf(x);
        const float y0f = floorf(y);
        const int ix0 = (int)x0f;
        const int iy0 = (int)y0f;
        const float wx1 = x - x0f;
        const float wy1 = y - y0f;
        const float wx0 = 1.0f - wx1;
        const float wy0 = 1.0f - wy1;

        const bool vx0 = (ix0 >= 0) && (ix0 <= Wv - 1);
        const bool vx1 = (ix0 + 1 >= 0) && (ix0 + 1 <= Wv - 1);
        const bool vy0 = (iy0 >= 0) && (iy0 <= Hv - 1);
        const bool vy1 = (iy0 + 1 >= 0) && (iy0 + 1 <= Hv - 1);

        const int cx0 = min(max(ix0, 0), Wv - 1);
        const int cx1 = min(max(ix0 + 1, 0), Wv - 1);
        const int cy0 = min(max(iy0, 0), Hv - 1);
        const int cy1 = min(max(iy0 + 1, 0), Hv - 1);

        const float w00 = (vx0 && vy0) ? (wx0 * wy0) : 0.0f;
        const float w01 = (vx1 && vy0) ? (wx1 * wy0) : 0.0f;
        const float w10 = (vx0 && vy1) ? (wx0 * wy1) : 0.0f;
        const float w11 = (vx1 && vy1) ? (wx1 * wy1) : 0.0f;

        const float4* p00 = (const float4*)(rbase + ((size_t)cy0 * Wv + cx0) * Cv);
        const float4* p01 = (const float4*)(rbase + ((size_t)cy0 * Wv + cx1) * Cv);
        const float4* p10 = (const float4*)(rbase + ((size_t)cy1 * Wv + cx0) * Cv);
        const float4* p11 = (const float4*)(rbase + ((size_t)cy1 * Wv + cx1) * Cv);

        const float4 g00 = p00[t];
        const float4 g01 = p01[t];
        const float4 g10 = p10[t];
        const float4 g11 = p11[t];

        float4 v;
        v.x = w00 * g00.x + w01 * g01.x + w10 * g10.x + w11 * g11.x;
        v.y = w00 * g00.y + w01 * g01.y + w10 * g10.y + w11 * g11.y;
        v.z = w00 * g00.z + w01 * g01.z + w10 * g10.z + w11 * g11.z;
        v.w = w00 * g00.w + w01 * g01.w + w10 * g10.w + w11 * g11.w;

        float s = L.x * v.x + L.y * v.y + L.z * v.z + L.w * v.w;

        // reduce across the 16 threads of this group (contiguous lanes)
        s += __shfl_xor_sync(0xffffffffu, s, 8);
        s += __shfl_xor_sync(0xffffffffu, s, 4);
        s += __shfl_xor_sync(0xffffffffu, s, 2);
        s += __shfl_xor_sync(0xffffffffu, s, 1);

        if ((lane & 15) == 0) {
            const int g = t >> 4;  // 0..3
            out[((size_t)(b * Gv + g) * Kv + k) * HW + pix] = s * (1.0f / GC);
        }
    }
}

extern "C" void kernel_launch(void* const* d_in, const int* in_sizes, int n_in,
                              void* d_out, int out_size) {
    const float* left  = (const float*)d_in[0];
    const float* right = (const float*)d_in[1];
    const float* flow  = (const float*)d_in[2];
    const float* extra = (const float*)d_in[3];
    float* out = (float*)d_out;

    float* d_right_nhwc;
    float* d_left_nhwc;
    cudaGetSymbolAddress((void**)&d_right_nhwc, g_right_nhwc);
    cudaGetSymbolAddress((void**)&d_left_nhwc, g_left_nhwc);

    {
        dim3 grid(Wv / 32, Cv / 32, Bv * Hv);
        dim3 block(32, 8);
        nchw_to_nhwc_kernel<<<grid, block>>>(right, d_right_nhwc);
        nchw_to_nhwc_kernel<<<grid, block>>>(left, d_left_nhwc);
    }
    {
        dim3 grid(Wv, Hv, Bv);
        corr_kernel<<<grid, 64>>>(flow, extra, out);
    }
}

// round 2
// speedup vs baseline: 1.4042x; 1.4042x over previous
#include <cuda_runtime.h>
#include <cuda_fp16.h>
#include <math.h>

#define Bv 2
#define Cv 256
#define Hv 96
#define Wv 192
#define Gv 4
#define Kv 9
#define GC (Cv / Gv)      // 64 channels per group
#define HW (Hv * Wv)      // 18432

// NHWC half scratch (allocation-free: __device__ globals). ~18.9MB each.
__device__ __half g_right_nhwc[(size_t)Bv * Hv * Wv * Cv];
__device__ __half g_left_nhwc[(size_t)Bv * Hv * Wv * Cv];

// ---------------------------------------------------------------------------
// NCHW fp32 -> NHWC fp16 transpose+convert. Per (b,h) slice: [C,W] -> [W,C].
// grid: (W/32, C/32, 2*B*H)  [z >= B*H selects left], block: (32, 8)
// ---------------------------------------------------------------------------
__global__ void nchw_to_nhwc_half_kernel(const float* __restrict__ right_in,
                                         const float* __restrict__ left_in) {
    __shared__ float tile[32][33];
    int z = blockIdx.z;
    int is_left = (z >= Bv * Hv);
    int bh = is_left ? (z - Bv * Hv) : z;
    int b = bh / Hv;
    int h = bh % Hv;
    const float* in = is_left ? left_in : right_in;
    __half* out = is_left ? g_left_nhwc : g_right_nhwc;

    const float* src = in + (size_t)b * Cv * HW + (size_t)h * Wv;
    int w0 = blockIdx.x * 32;
    int c0 = blockIdx.y * 32;
    int tx = threadIdx.x, ty = threadIdx.y;
#pragma unroll
    for (int i = 0; i < 32; i += 8) {
        tile[ty + i][tx] = src[(size_t)(c0 + ty + i) * HW + (w0 + tx)];
    }
    __syncthreads();
    __half* dst = out + (size_t)bh * Wv * Cv;
#pragma unroll
    for (int i = 0; i < 32; i += 8) {
        dst[(size_t)(w0 + ty + i) * Cv + (c0 + tx)] = __float2half(tile[tx][ty + i]);
    }
}

// 8-channel dot: g holds 8 halves, Lf is fp32 left vector
__device__ __forceinline__ float dot8(uint4 g, const float* __restrict__ Lf) {
    const __half2* h = (const __half2*)&g;
    float2 f0 = __half22float2(h[0]);
    float2 f1 = __half22float2(h[1]);
    float2 f2 = __half22float2(h[2]);
    float2 f3 = __half22float2(h[3]);
    float s = Lf[0] * f0.x;
    s = fmaf(Lf[1], f0.y, s);
    s = fmaf(Lf[2], f1.x, s);
    s = fmaf(Lf[3], f1.y, s);
    s = fmaf(Lf[4], f2.x, s);
    s = fmaf(Lf[5], f2.y, s);
    s = fmaf(Lf[6], f3.x, s);
    s = fmaf(Lf[7], f3.y, s);
    return s;
}

// ---------------------------------------------------------------------------
// Correlation kernel. 256-thread block = 4x2 pixel tile, 32 threads per pixel.
// Thread lane owns channels [8*lane, 8*lane+8) as uint4 of halves.
// Group g = lane/8 (8 threads x 8 ch = 64 ch); shfl reduction over 8 lanes.
// grid: (W/4, H/2, B)
// ---------------------------------------------------------------------------
__global__ __launch_bounds__(256) void corr_kernel(
    const float* __restrict__ flow,
    const float* __restrict__ extra,
    float* __restrict__ out)
{
    const int tid = threadIdx.x;
    const int lane = tid & 31;
    const int p = tid >> 5;                  // 0..7 pixel in tile
    const int w = blockIdx.x * 4 + (p & 3);
    const int h = blockIdx.y * 2 + (p >> 2);
    const int b = blockIdx.z;

    const int pix = h * Wv + w;

    // left vector (8 channels) -> fp32
    const uint4* leftp =
        (const uint4*)(g_left_nhwc + ((size_t)(b * Hv + h) * Wv + w) * Cv);
    uint4 Lu = leftp[lane];
    float Lf[8];
    {
        const __half2* lh = (const __half2*)&Lu;
#pragma unroll
        for (int i = 0; i < 4; i++) {
            float2 f = __half22float2(lh[i]);
            Lf[2 * i] = f.x;
            Lf[2 * i + 1] = f.y;
        }
    }

    const float fx = flow[(size_t)(b * 2 + 0) * HW + pix];
    const float fy = flow[(size_t)(b * 2 + 1) * HW + pix];
    const float bx = (float)w + fx;
    const float by = (float)h + fy;

    const __half* rbase = g_right_nhwc + (size_t)b * Hv * Wv * Cv;

#pragma unroll
    for (int k = 0; k < Kv; k++) {
        const float ex = extra[((size_t)(b * Kv + k) * 2 + 0) * HW + pix];
        const float ey = extra[((size_t)(b * Kv + k) * 2 + 1) * HW + pix];
        const float x = bx + (float)(k - 4) + ex;
        const float y = by + ey;

        const float x0f = floorf(x);
        const float y0f = floorf(y);
        const int ix0 = (int)x0f;
        const int iy0 = (int)y0f;
        const float wx1 = x - x0f;
        const float wy1 = y - y0f;
        const float wx0 = 1.0f - wx1;
        const float wy0 = 1.0f - wy1;

        const bool vx0 = (ix0 >= 0) && (ix0 <= Wv - 1);
        const bool vx1 = (ix0 + 1 >= 0) && (ix0 + 1 <= Wv - 1);
        const bool vy0 = (iy0 >= 0) && (iy0 <= Hv - 1);
        const bool vy1 = (iy0 + 1 >= 0) && (iy0 + 1 <= Hv - 1);

        const int cx0 = min(max(ix0, 0), Wv - 1);
        const int cx1 = min(max(ix0 + 1, 0), Wv - 1);
        const int cy0 = min(max(iy0, 0), Hv - 1);
        const int cy1 = min(max(iy0 + 1, 0), Hv - 1);

        const float w00 = (vx0 && vy0) ? (wx0 * wy0) : 0.0f;
        const float w01 = (vx1 && vy0) ? (wx1 * wy0) : 0.0f;
        const float w10 = (vx0 && vy1) ? (wx0 * wy1) : 0.0f;
        const float w11 = (vx1 && vy1) ? (wx1 * wy1) : 0.0f;

        const uint4* p00 = (const uint4*)(rbase + ((size_t)cy0 * Wv + cx0) * Cv);
        const uint4* p01 = (const uint4*)(rbase + ((size_t)cy0 * Wv + cx1) * Cv);
        const uint4* p10 = (const uint4*)(rbase + ((size_t)cy1 * Wv + cx0) * Cv);
        const uint4* p11 = (const uint4*)(rbase + ((size_t)cy1 * Wv + cx1) * Cv);

        const uint4 g00 = p00[lane];
        const uint4 g01 = p01[lane];
        const uint4 g10 = p10[lane];
        const uint4 g11 = p11[lane];

        float s = w00 * dot8(g00, Lf)
                + w01 * dot8(g01, Lf)
                + w10 * dot8(g10, Lf)
                + w11 * dot8(g11, Lf);

        // reduce across the 8 threads of this channel-group (contiguous lanes)
        s += __shfl_xor_sync(0xffffffffu, s, 4);
        s += __shfl_xor_sync(0xffffffffu, s, 2);
        s += __shfl_xor_sync(0xffffffffu, s, 1);

        if ((lane & 7) == 0) {
            const int g = lane >> 3;  // 0..3
            out[((size_t)(b * Gv + g) * Kv + k) * HW + pix] = s * (1.0f / GC);
        }
    }
}

extern "C" void kernel_launch(void* const* d_in, const int* in_sizes, int n_in,
                              void* d_out, int out_size) {
    const float* left  = (const float*)d_in[0];
    const float* right = (const float*)d_in[1];
    const float* flow  = (const float*)d_in[2];
    const float* extra = (const float*)d_in[3];
    float* out = (float*)d_out;

    {
        dim3 grid(Wv / 32, Cv / 32, 2 * Bv * Hv);
        dim3 block(32, 8);
        nchw_to_nhwc_half_kernel<<<grid, block>>>(right, left);
    }
    {
        dim3 grid(Wv / 4, Hv / 2, Bv);
        corr_kernel<<<grid, 256>>>(flow, extra, out);
    }
}

// round 3
// speedup vs baseline: 1.6958x; 1.2076x over previous
#include <cuda_runtime.h>
#include <cuda_fp16.h>
#include <math.h>

#define Bv 2
#define Cv 256
#define Hv 96
#define Wv 192
#define Gv 4
#define Kv 9
#define GC (Cv / Gv)      // 64 channels per group
#define HW (Hv * Wv)      // 18432

// NHWC half scratch (allocation-free: __device__ globals). ~18.9MB each.
__device__ __half g_right_nhwc[(size_t)Bv * Hv * Wv * Cv];
__device__ __half g_left_nhwc[(size_t)Bv * Hv * Wv * Cv];

static __device__ __forceinline__ __half2 u32_as_h2(unsigned int u) {
    __half2 h;
    *reinterpret_cast<unsigned int*>(&h) = u;
    return h;
}
static __device__ __forceinline__ unsigned int h2_as_u32(__half2 h) {
    return *reinterpret_cast<unsigned int*>(&h);
}

// ---------------------------------------------------------------------------
// NCHW fp32 -> NHWC fp16 transpose+convert. Tile: 64 channels x 32 w.
// grid: (W/32, C/64, 2*B*H)  [z >= B*H selects left], block: 256
// Stores are uint4 (8 halves) per thread.
// ---------------------------------------------------------------------------
__global__ __launch_bounds__(256) void nchw_to_nhwc_half_kernel(
    const float* __restrict__ right_in, const float* __restrict__ left_in)
{
    __shared__ float tile[64][33];
    const int tid = threadIdx.x;
    int z = blockIdx.z;
    int is_left = (z >= Bv * Hv);
    int bh = is_left ? (z - Bv * Hv) : z;
    int b = bh / Hv;
    int h = bh % Hv;
    const float* in = is_left ? left_in : right_in;
    __half* out = is_left ? g_left_nhwc : g_right_nhwc;

    const float* src = in + (size_t)b * Cv * HW + (size_t)h * Wv;
    const int w0 = blockIdx.x * 32;
    const int c0 = blockIdx.y * 64;
    const int tx = tid & 31;
    const int ty = tid >> 5;
#pragma unroll
    for (int i = 0; i < 8; i++) {
        int c = ty + i * 8;
        tile[c][tx] = src[(size_t)(c0 + c) * HW + (w0 + tx)];
    }
    __syncthreads();

    const int r = tid >> 3;        // 0..31  (w within tile)
    const int seg = tid & 7;       // 0..7   (8-channel segment)
    __half hv[8];
#pragma unroll
    for (int j = 0; j < 8; j++)
        hv[j] = __float2half(tile[seg * 8 + j][r]);
    __half* dst = out + ((size_t)bh * Wv + (w0 + r)) * Cv + c0 + seg * 8;
    *reinterpret_cast<uint4*>(dst) = *reinterpret_cast<uint4*>(hv);
}

// ---------------------------------------------------------------------------
// Correlation kernel. 256-thread block = 4x2 pixel tile, 32 threads/pixel.
// Phase 1: 72 threads precompute (pixel,k) gather offsets + splatted half2
//          weights into smem.
// Phase 2: lane owns 8 channels; 4-corner blend in HFMA2, dot in fp32,
//          8-lane shfl reduction per group.
// grid: (W/4, H/2, B)
// ---------------------------------------------------------------------------
__global__ __launch_bounds__(256) void corr_kernel(
    const float* __restrict__ flow,
    const float* __restrict__ extra,
    float* __restrict__ out)
{
    __shared__ int4  s_off[8 * Kv];
    __shared__ uint4 s_wgt[8 * Kv];

    const int tid = threadIdx.x;
    const int b = blockIdx.z;

    if (tid < 8 * Kv) {
        const int pi = tid / Kv;
        const int k = tid - pi * Kv;
        const int w = blockIdx.x * 4 + (pi & 3);
        const int h = blockIdx.y * 2 + (pi >> 2);
        const int pix = h * Wv + w;

        const float fx = flow[(size_t)(b * 2 + 0) * HW + pix];
        const float fy = flow[(size_t)(b * 2 + 1) * HW + pix];
        const float ex = extra[((size_t)(b * Kv + k) * 2 + 0) * HW + pix];
        const float ey = extra[((size_t)(b * Kv + k) * 2 + 1) * HW + pix];
        const float x = (float)w + fx + (float)(k - 4) + ex;
        const float y = (float)h + fy + ey;

        const float x0f = floorf(x);
        const float y0f = floorf(y);
        const int ix0 = (int)x0f;
        const int iy0 = (int)y0f;
        const float wx1 = x - x0f;
        const float wy1 = y - y0f;
        const float wx0 = 1.0f - wx1;
        const float wy0 = 1.0f - wy1;

        const bool vx0 = (ix0 >= 0) && (ix0 <= Wv - 1);
        const bool vx1 = (ix0 + 1 >= 0) && (ix0 + 1 <= Wv - 1);
        const bool vy0 = (iy0 >= 0) && (iy0 <= Hv - 1);
        const bool vy1 = (iy0 + 1 >= 0) && (iy0 + 1 <= Hv - 1);

        const int cx0 = min(max(ix0, 0), Wv - 1);
        const int cx1 = min(max(ix0 + 1, 0), Wv - 1);
        const int cy0 = min(max(iy0, 0), Hv - 1);
        const int cy1 = min(max(iy0 + 1, 0), Hv - 1);

        const float w00 = (vx0 && vy0) ? (wx0 * wy0) : 0.0f;
        const float w01 = (vx1 && vy0) ? (wx1 * wy0) : 0.0f;
        const float w10 = (vx0 && vy1) ? (wx0 * wy1) : 0.0f;
        const float w11 = (vx1 && vy1) ? (wx1 * wy1) : 0.0f;

        s_off[tid] = make_int4((cy0 * Wv + cx0) * Cv,
                               (cy0 * Wv + cx1) * Cv,
                               (cy1 * Wv + cx0) * Cv,
                               (cy1 * Wv + cx1) * Cv);
        s_wgt[tid] = make_uint4(h2_as_u32(__float2half2_rn(w00)),
                                h2_as_u32(__float2half2_rn(w01)),
                                h2_as_u32(__float2half2_rn(w10)),
                                h2_as_u32(__float2half2_rn(w11)));
    }
    __syncthreads();

    const int lane = tid & 31;
    const int p = tid >> 5;                  // 0..7 pixel in tile
    const int w = blockIdx.x * 4 + (p & 3);
    const int h = blockIdx.y * 2 + (p >> 2);
    const int pix = h * Wv + w;

    // left vector (8 channels) -> fp32
    const __half* lptr = g_left_nhwc + ((size_t)(b * Hv + h) * Wv + w) * Cv + lane * 8;
    uint4 Lu = *reinterpret_cast<const uint4*>(lptr);
    float Lf[8];
    {
        const __half2* lh = (const __half2*)&Lu;
#pragma unroll
        for (int i = 0; i < 4; i++) {
            float2 f = __half22float2(lh[i]);
            Lf[2 * i] = f.x;
            Lf[2 * i + 1] = f.y;
        }
    }

    const __half* rbase = g_right_nhwc + (size_t)b * HW * Cv + lane * 8;

#pragma unroll
    for (int k = 0; k < Kv; k++) {
        const int4 off = s_off[p * Kv + k];
        const uint4 wg = s_wgt[p * Kv + k];
        const __half2 w00 = u32_as_h2(wg.x);
        const __half2 w01 = u32_as_h2(wg.y);
        const __half2 w10 = u32_as_h2(wg.z);
        const __half2 w11 = u32_as_h2(wg.w);

        const uint4 g00 = *reinterpret_cast<const uint4*>(rbase + off.x);
        const uint4 g01 = *reinterpret_cast<const uint4*>(rbase + off.y);
        const uint4 g10 = *reinterpret_cast<const uint4*>(rbase + off.z);
        const uint4 g11 = *reinterpret_cast<const uint4*>(rbase + off.w);

        const __half2* a = (const __half2*)&g00;
        const __half2* c = (const __half2*)&g01;
        const __half2* d = (const __half2*)&g10;
        const __half2* e = (const __half2*)&g11;

        float s0 = 0.0f, s1 = 0.0f;
#pragma unroll
        for (int j = 0; j < 4; j++) {
            __half2 v = __hmul2(w00, a[j]);
            v = __hfma2(w01, c[j], v);
            v = __hfma2(w10, d[j], v);
            v = __hfma2(w11, e[j], v);
            float2 f = __half22float2(v);
            s0 = fmaf(Lf[2 * j], f.x, s0);
            s1 = fmaf(Lf[2 * j + 1], f.y, s1);
        }
        float s = s0 + s1;

        // reduce across the 8 threads of this channel-group (contiguous lanes)
        s += __shfl_xor_sync(0xffffffffu, s, 4);
        s += __shfl_xor_sync(0xffffffffu, s, 2);
        s += __shfl_xor_sync(0xffffffffu, s, 1);

        if ((lane & 7) == 0) {
            const int g = lane >> 3;  // 0..3
            out[((size_t)(b * Gv + g) * Kv + k) * HW + pix] = s * (1.0f / GC);
        }
    }
}

extern "C" void kernel_launch(void* const* d_in, const int* in_sizes, int n_in,
                              void* d_out, int out_size) {
    const float* left  = (const float*)d_in[0];
    const float* right = (const float*)d_in[1];
    const float* flow  = (const float*)d_in[2];
    const float* extra = (const float*)d_in[3];
    float* out = (float*)d_out;

    {
        dim3 grid(Wv / 32, Cv / 64, 2 * Bv * Hv);
        nchw_to_nhwc_half_kernel<<<grid, 256>>>(right, left);
    }
    {
        dim3 grid(Wv / 4, Hv / 2, Bv);
        corr_kernel<<<grid, 256>>>(flow, extra, out);
    }
}